// round 16
// baseline (speedup 1.0000x reference)
#include <cuda_runtime.h>
#include <cuda_fp16.h>
#include <cstdint>

#define N_NODES 50000
#define N_EDGES 600000
#define N_RELS  19
#define D_IN    128
#define D_HID   64
#define D_OUT   2
#define ECH     128                    // edges per chunk (full M tile)
#define NCH     8                      // chunks per CTA
#define EGRID   ((N_EDGES + ECH * NCH - 1) / (ECH * NCH) + N_RELS)  // 605
#define SLGRID  ((N_NODES + ECH * NCH - 1) / (ECH * NCH))           // 49

// Scratch (device globals — no allocation allowed in kernel_launch)
__device__ float g_h1[(size_t)N_NODES * D_HID];
__device__ float g_T2[(size_t)N_NODES * N_RELS * D_OUT];   // 7.6 MB
__device__ int   g_cnt[N_RELS];
__device__ int   g_off[N_RELS + 1];
__device__ int   g_cbase[N_RELS + 1];
__device__ int   g_fill[N_RELS];
__device__ int   g_done;
__device__ int   g_esrc[N_EDGES];
__device__ int   g_edst[N_EDGES];
// Preconverted fp16 operands: A single plane; W single fp16 plane per rel.
__device__ __align__(256) __half g_featF[(size_t)N_NODES * D_IN];   // 12.8 MB
#define PITCH 136
#define WIMG (64 * PITCH)               // halves per rel = 17408 B
__device__ __align__(256) __half g_wimg[20 * WIMG];

// ===========================================================================
__device__ __forceinline__ uint32_t smem_u32(const void* p) {
  uint32_t a;
  asm("{ .reg .u64 t; cvta.to.shared.u64 t, %1; cvt.u32.u64 %0, t; }"
      : "=r"(a) : "l"(p));
  return a;
}
#define LDSM_X4(r, addr)                                                    \
  asm volatile("ldmatrix.sync.aligned.m8n8.x4.shared.b16 {%0,%1,%2,%3}, [%4];" \
               : "=r"((r)[0]), "=r"((r)[1]), "=r"((r)[2]), "=r"((r)[3])     \
               : "r"(addr))
#define MMA_F16(d, a, b0, b1)                                               \
  asm volatile("mma.sync.aligned.m16n8k16.row.col.f32.f16.f16.f32 "         \
               "{%0,%1,%2,%3}, {%4,%5,%6,%7}, {%8,%9}, {%0,%1,%2,%3};"      \
               : "+f"((d)[0]), "+f"((d)[1]), "+f"((d)[2]), "+f"((d)[3])     \
               : "r"((a)[0]), "r"((a)[1]), "r"((a)[2]), "r"((a)[3]),        \
                 "r"(b0), "r"(b1))
#define CP16(dst, src)                                                      \
  asm volatile("cp.async.cg.shared.global [%0], [%1], 16;"                  \
               :: "r"(dst), "l"(src) : "memory")
#define CP_COMMIT() asm volatile("cp.async.commit_group;" ::: "memory")
#define CP_WAIT0()  asm volatile("cp.async.wait_group 0;" ::: "memory")
#define REDV2(p, a, b)                                                      \
  asm volatile("red.global.add.v2.f32 [%0], {%1,%2};"                      \
               :: "l"(p), "f"(a), "f"(b) : "memory")
#define REDV4(p, v)                                                         \
  asm volatile("red.global.add.v4.f32 [%0], {%1,%2,%3,%4};"                 \
               :: "l"(p), "f"((v).x), "f"((v).y), "f"((v).z), "f"((v).w)   \
               : "memory")

// SMEM: B plane (fp16), then ONE A buffer (fp16, 128 rows). 52224 B total
// -> 4 CTAs/SM (208896 B of 228 KB).
#define S_B   0
#define S_A0  (64 * PITCH * 2)                  // 17408
#define S_FTOT (S_A0 + 128 * PITCH * 2)         // 52224

// ---------------------------------------------------------------------------
// Prep: feat -> fp16; W1+loop1 -> fp16 image; zero g_h1 + counters.
// ---------------------------------------------------------------------------
#define FEAT_F4 (N_NODES * 32)
#define W_F4    (20 * 2048)
#define H1_F4   (N_NODES * D_HID / 4)
#define PREP_TOT (FEAT_F4 + W_F4 + H1_F4)

__global__ void __launch_bounds__(256) k_prep(
    const float* __restrict__ feat, const float* __restrict__ W1,
    const float* __restrict__ loop1) {
  int i = blockIdx.x * 256 + threadIdx.x;
  if (i < 21) {
    if (i < N_RELS) g_cnt[i] = 0;
    if (i == 20) g_done = 0;
  }
  if (i < FEAT_F4) {
    float4 v = *(const float4*)(feat + (size_t)i * 4);
    __half2 h01 = __floats2half2_rn(v.x, v.y);
    __half2 h23 = __floats2half2_rn(v.z, v.w);
    uint2 pk;
    pk.x = *(uint32_t*)&h01; pk.y = *(uint32_t*)&h23;
    *(uint2*)((char*)g_featF + (size_t)i * 8) = pk;
  } else if (i < FEAT_F4 + W_F4) {
    int j = i - FEAT_F4;
    int rel = j >> 11, rem = j & 2047;
    int k = rem >> 4, o4 = rem & 15;
    const float* srcp = (rel < N_RELS) ? (W1 + ((size_t)rel * D_IN + k) * D_HID)
                                       : (loop1 + (size_t)k * D_HID);
    float4 v = *(const float4*)(srcp + o4 * 4);
    float x[4] = {v.x, v.y, v.z, v.w};
    __half* img = g_wimg + (size_t)rel * WIMG;
    #pragma unroll
    for (int jj = 0; jj < 4; jj++)
      img[(o4 * 4 + jj) * PITCH + k] = __float2half_rn(x[jj]);
  } else if (i < PREP_TOT) {
    int j = i - FEAT_F4 - W_F4;
    *(float4*)(g_h1 + (size_t)j * 4) = make_float4(0.f, 0.f, 0.f, 0.f);
  }
}

// ---------------------------------------------------------------------------
// Hist + prefix (done-counter; last block computes offsets + CTA bases).
// ---------------------------------------------------------------------------
__global__ void __launch_bounds__(512) k_histprefix(const int* __restrict__ et) {
  __shared__ int lh[N_RELS];
  if (threadIdx.x < N_RELS) lh[threadIdx.x] = 0;
  __syncthreads();
  int base = blockIdx.x * 2048;
  #pragma unroll
  for (int j = 0; j < 4; j++) {
    int e = base + j * 512 + threadIdx.x;
    if (e < N_EDGES) atomicAdd(&lh[__ldg(et + e)], 1);
  }
  __syncthreads();
  if (threadIdx.x < N_RELS && lh[threadIdx.x])
    atomicAdd(&g_cnt[threadIdx.x], lh[threadIdx.x]);
  __threadfence();
  __syncthreads();
  if (threadIdx.x == 0) {
    int old = atomicAdd(&g_done, 1);
    if (old == (int)gridDim.x - 1) {
      int o = 0, cb = 0;
      for (int r = 0; r < N_RELS; r++) {
        g_off[r] = o; g_fill[r] = o; g_cbase[r] = cb;
        cb += (g_cnt[r] + ECH * NCH - 1) / (ECH * NCH);
        o += g_cnt[r];
      }
      g_off[N_RELS] = o; g_cbase[N_RELS] = cb;
    }
  }
}

__global__ void __launch_bounds__(512) k_scatter(
    const int* __restrict__ src, const int* __restrict__ dst,
    const int* __restrict__ et) {
  __shared__ int lh[N_RELS], lbase[N_RELS];
  if (threadIdx.x < N_RELS) lh[threadIdx.x] = 0;
  __syncthreads();
  int base = blockIdx.x * 2048;
  int r[4], s[4], d[4], idx[4];
  #pragma unroll
  for (int j = 0; j < 4; j++) {
    int e = base + j * 512 + threadIdx.x;
    r[j] = -1;
    if (e < N_EDGES) {
      r[j] = __ldg(et + e); s[j] = __ldg(src + e); d[j] = __ldg(dst + e);
      idx[j] = atomicAdd(&lh[r[j]], 1);
    }
  }
  __syncthreads();
  if (threadIdx.x < N_RELS)
    lbase[threadIdx.x] = lh[threadIdx.x]
        ? atomicAdd(&g_fill[threadIdx.x], lh[threadIdx.x]) : 0;
  __syncthreads();
  #pragma unroll
  for (int j = 0; j < 4; j++)
    if (r[j] >= 0) {
      int pos = lbase[r[j]] + idx[j];
      g_esrc[pos] = s[j]; g_edst[pos] = d[j];
    }
}

// ---------------------------------------------------------------------------
// 128x64 pure-fp16 MMA core: per k-step 4 LDSM -> 8 MMA.
// Warp tile 32(M) x 32(N), 4x2 warp grid.
// ---------------------------------------------------------------------------
__device__ __forceinline__ void mma_core(uint32_t sb, int wid, int lane,
                                         float acc[2][4][4]) {
  const int mrow = (wid & 3) * 32, ncol = (wid >> 2) * 32;
  const int lr = lane & 15, lc = lane >> 4;
  const uint32_t a0 = sb + S_A0 + ((uint32_t)(mrow + lr) * PITCH + lc * 8) * 2;
  const uint32_t a1 = a0 + 16 * PITCH * 2;
  const uint32_t b0 = sb + S_B + ((uint32_t)(ncol + lr) * PITCH + lc * 8) * 2;
  const uint32_t b1 = b0 + 16 * PITCH * 2;
  #pragma unroll
  for (int mi = 0; mi < 2; mi++)
    #pragma unroll
    for (int ni = 0; ni < 4; ni++)
      #pragma unroll
      for (int c = 0; c < 4; c++) acc[mi][ni][c] = 0.f;

  #pragma unroll
  for (int k0 = 0; k0 < 8; k0++) {
    const uint32_t ka = (uint32_t)k0 * 32;
    uint32_t A0[4], A1[4], B0[4], B1[4];
    LDSM_X4(A0, a0 + ka); LDSM_X4(A1, a1 + ka);
    LDSM_X4(B0, b0 + ka); LDSM_X4(B1, b1 + ka);
    MMA_F16(acc[0][0], A0, B0[0], B0[2]);
    MMA_F16(acc[0][1], A0, B0[1], B0[3]);
    MMA_F16(acc[0][2], A0, B1[0], B1[2]);
    MMA_F16(acc[0][3], A0, B1[1], B1[3]);
    MMA_F16(acc[1][0], A1, B0[0], B0[2]);
    MMA_F16(acc[1][1], A1, B0[1], B0[3]);
    MMA_F16(acc[1][2], A1, B1[0], B1[2]);
    MMA_F16(acc[1][3], A1, B1[1], B1[3]);
  }
}

// ---------------------------------------------------------------------------
// Fused layer-1: each CTA = up to 8 chunks x 128 edges of ONE relation.
// B staged once; single A buffer, stage(c+1) after mma-sync overlaps the
// epilogue. 4 CTAs/SM. Epilogue: shfl pair-merge -> red.global.add.v4.
// ---------------------------------------------------------------------------
__global__ void __launch_bounds__(256, 4) k_edge1_fused(
    const float* __restrict__ b1) {
  extern __shared__ char sm[];
  const uint32_t sb = smem_u32(sm);
  const int tid = threadIdx.x, wid = tid >> 5, lane = tid & 31;
  const int b = blockIdx.x;
  const int gridE = (int)gridDim.x - SLGRID;
  const bool is_edge = (b < gridE);

  int r, eoff = 0, eend = 0, cstart = 0, nch, n0 = 0;
  if (is_edge) {
    if (b >= __ldg(&g_cbase[N_RELS])) return;
    r = 0;
    while (b >= __ldg(&g_cbase[r + 1])) r++;
    eoff = __ldg(&g_off[r]);
    const int cnt = __ldg(&g_cnt[r]);
    eend = eoff + cnt;
    cstart = (b - __ldg(&g_cbase[r])) * NCH;
    nch = min(NCH, (cnt + ECH - 1) / ECH - cstart);
  } else {
    const int sl = b - gridE;
    r = N_RELS;
    n0 = sl * (NCH * ECH);
    nch = min(NCH, (N_NODES - n0 + ECH - 1) / ECH);
  }

  // Stage A chunk c: 128 rows x 16 x 16B cp.async (single buffer).
  auto stageA = [&](int c) {
    int ebase = 0, mm = 0;
    if (is_edge) {
      ebase = eoff + (cstart + c) * ECH;
      mm = min(ECH, eend - ebase);
    }
    #pragma unroll
    for (int t = 0; t < 8; t++) {
      int idx = tid + t * 256;
      int row = idx >> 4, cc = idx & 15;
      int s = is_edge ? __ldg(&g_esrc[ebase + min(row, mm - 1)])
                      : min(n0 + c * ECH + row, N_NODES - 1);
      CP16(sb + S_A0 + (uint32_t)row * (PITCH * 2) + (uint32_t)cc * 16,
           (const char*)g_featF + (size_t)s * 256 + cc * 16);
    }
  };

  // Prologue: B (1088 x 16B) + A0 in group 0.
  const char* wsrc = (const char*)(g_wimg + (size_t)r * WIMG);
  #pragma unroll
  for (int t = 0; t < 5; t++) {
    int idx = tid + t * 256;
    if (idx < WIMG * 2 / 16)
      CP16(sb + S_B + idx * 16, wsrc + idx * 16);
  }
  stageA(0);
  CP_COMMIT();

  const int g = lane >> 2, tq = lane & 3;
  const int mrow = (wid & 3) * 32, ncol = (wid >> 2) * 32;
  const int odd = tq & 1;                 // lane-pair role
  const int col4 = ncol + (tq >> 1) * 4;  // + ni*8 later

  for (int c = 0; c < nch; c++) {
    CP_WAIT0();
    __syncthreads();                 // A[c] (and B) visible
    float acc[2][4][4];
    mma_core(sb, wid, lane, acc);
    __syncthreads();                 // all warps done reading A[c]
    if (c + 1 < nch) { stageA(c + 1); CP_COMMIT(); }  // overlaps epilogue

    if (is_edge) {
      const int ebase = eoff + (cstart + c) * ECH;
      const int m = min(ECH, eend - ebase);
      #pragma unroll
      for (int mi = 0; mi < 2; mi++) {
        int row = mrow + mi * 16 + g + (odd ? 8 : 0);
        int d = (row < m) ? __ldg(&g_edst[ebase + row]) : -1;
        #pragma unroll
        for (int ni = 0; ni < 4; ni++) {
          float o0 = __shfl_xor_sync(0xffffffffu, acc[mi][ni][0], 1);
          float o1 = __shfl_xor_sync(0xffffffffu, acc[mi][ni][1], 1);
          float o2 = __shfl_xor_sync(0xffffffffu, acc[mi][ni][2], 1);
          float o3 = __shfl_xor_sync(0xffffffffu, acc[mi][ni][3], 1);
          if (d >= 0) {
            float4 v = odd
                ? make_float4(o2, o3, acc[mi][ni][2], acc[mi][ni][3])
                : make_float4(acc[mi][ni][0], acc[mi][ni][1], o0, o1);
            REDV4(g_h1 + (size_t)d * D_HID + col4 + ni * 8, v);
          }
        }
      }
    } else {
      const int nb = n0 + c * ECH;
      #pragma unroll
      for (int mi = 0; mi < 2; mi++) {
        int n = nb + mrow + mi * 16 + g + (odd ? 8 : 0);
        #pragma unroll
        for (int ni = 0; ni < 4; ni++) {
          float4 bias4 = __ldg((const float4*)(b1 + col4 + ni * 8));
          float o0 = __shfl_xor_sync(0xffffffffu, acc[mi][ni][0], 1);
          float o1 = __shfl_xor_sync(0xffffffffu, acc[mi][ni][1], 1);
          float o2 = __shfl_xor_sync(0xffffffffu, acc[mi][ni][2], 1);
          float o3 = __shfl_xor_sync(0xffffffffu, acc[mi][ni][3], 1);
          if (n < N_NODES) {
            float4 v = odd
                ? make_float4(o2 + bias4.x, o3 + bias4.y,
                              acc[mi][ni][2] + bias4.z,
                              acc[mi][ni][3] + bias4.w)
                : make_float4(acc[mi][ni][0] + bias4.x,
                              acc[mi][ni][1] + bias4.y,
                              o0 + bias4.z, o1 + bias4.w);
            REDV4(g_h1 + (size_t)n * D_HID + col4 + ni * 8, v);
          }
        }
      }
    }
  }
}

// ---------------------------------------------------------------------------
// Layer-2 node transform: T2[n][r][:] = relu(h1[n]) @ W2[r] for all rels,
// and out[n] = relu(h1[n]) @ loop2 + b2 (direct store, no atomics).
// Block = 64 nodes, 256 threads (4 rel-groups of 5 rels per node).
// ---------------------------------------------------------------------------
__global__ void __launch_bounds__(256) k_layer2(
    const float* __restrict__ W2, const float* __restrict__ loop2,
    const float* __restrict__ b2, float* __restrict__ out) {
  __shared__ float sH[64][65];
  __shared__ float sW[N_RELS * D_HID * D_OUT];
  __shared__ float sL[D_HID * D_OUT + D_OUT];
  const int n0 = blockIdx.x * 64;

  for (int i = threadIdx.x; i < N_RELS * D_HID * D_OUT; i += 256) sW[i] = W2[i];
  for (int i = threadIdx.x; i < D_HID * D_OUT; i += 256) sL[i] = loop2[i];
  if (threadIdx.x < D_OUT) sL[D_HID * D_OUT + threadIdx.x] = b2[threadIdx.x];
  for (int i = threadIdx.x; i < 64 * D_HID; i += 256) {
    int n = i >> 6, k = i & 63;
    float v = 0.f;
    if (n0 + n < N_NODES) v = g_h1[(size_t)(n0 + n) * D_HID + k];
    sH[n][k] = fmaxf(v, 0.f);
  }
  __syncthreads();

  const int node = threadIdx.x >> 2;
  const int rg   = threadIdx.x & 3;
  float acc[5][2] = {};
  float s0 = 0.f, s1 = 0.f;
  for (int k = 0; k < D_HID; k++) {
    float f = sH[node][k];
    #pragma unroll
    for (int i = 0; i < 5; i++) {
      int r = rg + 4 * i;
      if (r < N_RELS) {
        acc[i][0] += f * sW[(r * D_HID + k) * 2];
        acc[i][1] += f * sW[(r * D_HID + k) * 2 + 1];
      }
    }
    if (rg == 0) { s0 += f * sL[k * 2]; s1 += f * sL[k * 2 + 1]; }
  }

  int n = n0 + node;
  if (n < N_NODES) {
    #pragma unroll
    for (int i = 0; i < 5; i++) {
      int r = rg + 4 * i;
      if (r < N_RELS)
        *(float2*)&g_T2[((size_t)n * N_RELS + r) * D_OUT] =
            make_float2(acc[i][0], acc[i][1]);
    }
    if (rg == 0)
      *(float2*)&out[(size_t)n * D_OUT] =
          make_float2(s0 + sL[D_HID * D_OUT], s1 + sL[D_HID * D_OUT + 1]);
  }
}

// ---------------------------------------------------------------------------
// Layer-2 edge reduce: 8B gather from T2 per edge + red.v2 (measured ~10us).
// Uses bucketed edge arrays; rel from 19-entry smem offset scan.
// ---------------------------------------------------------------------------
__global__ void __launch_bounds__(256) k_edge2(float* __restrict__ out) {
  __shared__ int so[N_RELS + 1];
  if (threadIdx.x < N_RELS + 1) so[threadIdx.x] = g_off[threadIdx.x];
  __syncthreads();
  int e = blockIdx.x * 256 + threadIdx.x;
  if (e >= N_EDGES) return;
  int r = 0;
  #pragma unroll
  for (int rr = 1; rr < N_RELS; rr++)
    if (e >= so[rr]) r = rr;
  int s = __ldg(&g_esrc[e]), d = __ldg(&g_edst[e]);
  const float2 v = *(const float2*)(g_T2 + ((size_t)s * N_RELS + r) * D_OUT);
  REDV2(out + (size_t)d * D_OUT, v.x, v.y);
}

// ---------------------------------------------------------------------------
extern "C" void kernel_launch(void* const* d_in, const int* in_sizes, int n_in,
                              void* d_out, int out_size) {
  const float* feat  = (const float*)d_in[0];
  const float* W1    = (const float*)d_in[1];
  const float* loop1 = (const float*)d_in[2];
  const float* b1    = (const float*)d_in[3];
  const float* W2    = (const float*)d_in[4];
  const float* loop2 = (const float*)d_in[5];
  const float* b2    = (const float*)d_in[6];
  const int*   src   = (const int*)d_in[7];
  const int*   dst   = (const int*)d_in[8];
  const int*   et    = (const int*)d_in[9];
  float* out = (float*)d_out;

  cudaFuncSetAttribute(k_edge1_fused,
                       cudaFuncAttributeMaxDynamicSharedMemorySize, S_FTOT);

  // 1: prep   2: hist+prefix   3: scatter
  k_prep<<<(PREP_TOT + 255) / 256, 256>>>(feat, W1, loop1);
  k_histprefix<<<(N_EDGES + 2047) / 2048, 512>>>(et);
  k_scatter<<<(N_EDGES + 2047) / 2048, 512>>>(src, dst, et);

  // 4: fused pipelined edge GEMM + self-loop (profiled slot)
  k_edge1_fused<<<EGRID + SLGRID, 256, S_FTOT>>>(b1);

  // 5: per-node layer-2 transform (T2 + out self term)
  k_layer2<<<(N_NODES + 63) / 64, 256>>>(W2, loop2, b2, out);

  // 6: per-edge 8B gather + reduce
  k_edge2<<<(N_EDGES + 255) / 256, 256>>>(out);
}

// round 17
// speedup vs baseline: 1.2242x; 1.2242x over previous
#include <cuda_runtime.h>
#include <cuda_fp16.h>
#include <cstdint>

#define N_NODES 50000
#define N_EDGES 600000
#define N_RELS  19
#define D_IN    128
#define D_HID   64
#define D_OUT   2
#define ECH     128                    // edges per chunk (full M tile)
#define NCH     9                      // chunks per CTA (grid fits one wave)
#define EGRID   ((N_EDGES + ECH * NCH - 1) / (ECH * NCH) + N_RELS)  // 540
#define SLGRID  ((N_NODES + ECH * NCH - 1) / (ECH * NCH))           // 44
#define EB      ((N_EDGES + 255) / 256)   // edge blocks in k_layer2
#define NB      ((N_NODES + 255) / 256)   // node (self-term) blocks

// Scratch (device globals — no allocation allowed in kernel_launch)
__device__ float g_h1[(size_t)N_NODES * D_HID];
__device__ int   g_cnt[N_RELS];
__device__ int   g_off[N_RELS + 1];
__device__ int   g_cbase[N_RELS + 1];
__device__ int   g_fill[N_RELS];
__device__ int   g_done;
__device__ volatile int g_ready;
__device__ int   g_esrc[N_EDGES];
__device__ int   g_edst[N_EDGES];
// Preconverted fp16 operands: A single plane; W single fp16 plane per rel.
__device__ __align__(256) __half g_featF[(size_t)N_NODES * D_IN];   // 12.8 MB
#define PITCH 136
#define WIMG (64 * PITCH)               // halves per rel = 17408 B
__device__ __align__(256) __half g_wimg[20 * WIMG];

// ===========================================================================
__device__ __forceinline__ uint32_t smem_u32(const void* p) {
  uint32_t a;
  asm("{ .reg .u64 t; cvta.to.shared.u64 t, %1; cvt.u32.u64 %0, t; }"
      : "=r"(a) : "l"(p));
  return a;
}
#define LDSM_X4(r, addr)                                                    \
  asm volatile("ldmatrix.sync.aligned.m8n8.x4.shared.b16 {%0,%1,%2,%3}, [%4];" \
               : "=r"((r)[0]), "=r"((r)[1]), "=r"((r)[2]), "=r"((r)[3])     \
               : "r"(addr))
#define MMA_F16(d, a, b0, b1)                                               \
  asm volatile("mma.sync.aligned.m16n8k16.row.col.f32.f16.f16.f32 "         \
               "{%0,%1,%2,%3}, {%4,%5,%6,%7}, {%8,%9}, {%0,%1,%2,%3};"      \
               : "+f"((d)[0]), "+f"((d)[1]), "+f"((d)[2]), "+f"((d)[3])     \
               : "r"((a)[0]), "r"((a)[1]), "r"((a)[2]), "r"((a)[3]),        \
                 "r"(b0), "r"(b1))
#define CP16(dst, src)                                                      \
  asm volatile("cp.async.cg.shared.global [%0], [%1], 16;"                  \
               :: "r"(dst), "l"(src) : "memory")
#define CP_COMMIT() asm volatile("cp.async.commit_group;" ::: "memory")
#define CP_WAIT0()  asm volatile("cp.async.wait_group 0;" ::: "memory")
#define REDV2(p, a, b)                                                      \
  asm volatile("red.global.add.v2.f32 [%0], {%1,%2};"                      \
               :: "l"(p), "f"(a), "f"(b) : "memory")
#define REDV4(p, v)                                                         \
  asm volatile("red.global.add.v4.f32 [%0], {%1,%2,%3,%4};"                 \
               :: "l"(p), "f"((v).x), "f"((v).y), "f"((v).z), "f"((v).w)   \
               : "memory")

// SMEM: B plane (fp16), then ONE A buffer (fp16, 128 rows). 52224 B total
// -> 4 CTAs/SM (208896 B of 228 KB).
#define S_B   0
#define S_A0  (64 * PITCH * 2)                  // 17408
#define S_FTOT (S_A0 + 128 * PITCH * 2)         // 52224

// ---------------------------------------------------------------------------
// Prep: feat -> fp16; W1+loop1 -> fp16 image; zero g_h1 + out + counters.
// ---------------------------------------------------------------------------
#define FEAT_F4 (N_NODES * 32)
#define W_F4    (20 * 2048)
#define H1_F4   (N_NODES * D_HID / 4)
#define OUT_F4  (N_NODES * D_OUT / 4)
#define PREP_TOT (FEAT_F4 + W_F4 + H1_F4 + OUT_F4)

__global__ void __launch_bounds__(256) k_prep(
    const float* __restrict__ feat, const float* __restrict__ W1,
    const float* __restrict__ loop1, float* __restrict__ out) {
  int i = blockIdx.x * 256 + threadIdx.x;
  if (i < 22) {
    if (i < N_RELS) g_cnt[i] = 0;
    if (i == 20) g_done = 0;
    if (i == 21) g_ready = 0;
  }
  if (i < FEAT_F4) {
    float4 v = *(const float4*)(feat + (size_t)i * 4);
    __half2 h01 = __floats2half2_rn(v.x, v.y);
    __half2 h23 = __floats2half2_rn(v.z, v.w);
    uint2 pk;
    pk.x = *(uint32_t*)&h01; pk.y = *(uint32_t*)&h23;
    *(uint2*)((char*)g_featF + (size_t)i * 8) = pk;
  } else if (i < FEAT_F4 + W_F4) {
    int j = i - FEAT_F4;
    int rel = j >> 11, rem = j & 2047;
    int k = rem >> 4, o4 = rem & 15;
    const float* srcp = (rel < N_RELS) ? (W1 + ((size_t)rel * D_IN + k) * D_HID)
                                       : (loop1 + (size_t)k * D_HID);
    float4 v = *(const float4*)(srcp + o4 * 4);
    float x[4] = {v.x, v.y, v.z, v.w};
    __half* img = g_wimg + (size_t)rel * WIMG;
    #pragma unroll
    for (int jj = 0; jj < 4; jj++)
      img[(o4 * 4 + jj) * PITCH + k] = __float2half_rn(x[jj]);
  } else if (i < FEAT_F4 + W_F4 + H1_F4) {
    int j = i - FEAT_F4 - W_F4;
    *(float4*)(g_h1 + (size_t)j * 4) = make_float4(0.f, 0.f, 0.f, 0.f);
  } else if (i < PREP_TOT) {
    int j = i - FEAT_F4 - W_F4 - H1_F4;
    *(float4*)(out + (size_t)j * 4) = make_float4(0.f, 0.f, 0.f, 0.f);
  }
}

// ---------------------------------------------------------------------------
// Bucket: hist + prefix + scatter in ONE kernel. 293 blocks (all co-resident:
// 293 < 592 slots), last-done block publishes offsets + g_ready; all blocks
// spin on g_ready then scatter using their pass-1 local indices.
// ---------------------------------------------------------------------------
__global__ void __launch_bounds__(512) k_bucket(
    const int* __restrict__ src, const int* __restrict__ dst,
    const int* __restrict__ et) {
  __shared__ int lh[N_RELS], lbase[N_RELS];
  const int tid = threadIdx.x;
  if (tid < N_RELS) lh[tid] = 0;
  __syncthreads();
  int base = blockIdx.x * 2048;
  int r[4], s[4], d[4], idx[4];
  #pragma unroll
  for (int j = 0; j < 4; j++) {
    int e = base + j * 512 + tid;
    r[j] = -1;
    if (e < N_EDGES) {
      r[j] = __ldg(et + e); s[j] = __ldg(src + e); d[j] = __ldg(dst + e);
      idx[j] = atomicAdd(&lh[r[j]], 1);
    }
  }
  __syncthreads();
  if (tid < N_RELS && lh[tid]) atomicAdd(&g_cnt[tid], lh[tid]);
  __threadfence();
  __syncthreads();
  if (tid == 0) {
    int old = atomicAdd(&g_done, 1);
    if (old == (int)gridDim.x - 1) {
      int o = 0, cb = 0;
      for (int rr = 0; rr < N_RELS; rr++) {
        g_off[rr] = o; g_fill[rr] = o; g_cbase[rr] = cb;
        cb += (g_cnt[rr] + ECH * NCH - 1) / (ECH * NCH);
        o += g_cnt[rr];
      }
      g_off[N_RELS] = o; g_cbase[N_RELS] = cb;
      __threadfence();
      g_ready = 1;
    }
    while (g_ready == 0) { }       // all 293 blocks co-resident -> safe
  }
  __syncthreads();
  if (tid < N_RELS)
    lbase[tid] = lh[tid] ? atomicAdd(&g_fill[tid], lh[tid]) : 0;
  __syncthreads();
  #pragma unroll
  for (int j = 0; j < 4; j++)
    if (r[j] >= 0) {
      int pos = lbase[r[j]] + idx[j];
      g_esrc[pos] = s[j]; g_edst[pos] = d[j];
    }
}

// ---------------------------------------------------------------------------
// 128x64 pure-fp16 MMA core: per k-step 4 LDSM -> 8 MMA.
// Warp tile 32(M) x 32(N), 4x2 warp grid.
// ---------------------------------------------------------------------------
__device__ __forceinline__ void mma_core(uint32_t sb, int wid, int lane,
                                         float acc[2][4][4]) {
  const int mrow = (wid & 3) * 32, ncol = (wid >> 2) * 32;
  const int lr = lane & 15, lc = lane >> 4;
  const uint32_t a0 = sb + S_A0 + ((uint32_t)(mrow + lr) * PITCH + lc * 8) * 2;
  const uint32_t a1 = a0 + 16 * PITCH * 2;
  const uint32_t b0 = sb + S_B + ((uint32_t)(ncol + lr) * PITCH + lc * 8) * 2;
  const uint32_t b1 = b0 + 16 * PITCH * 2;
  #pragma unroll
  for (int mi = 0; mi < 2; mi++)
    #pragma unroll
    for (int ni = 0; ni < 4; ni++)
      #pragma unroll
      for (int c = 0; c < 4; c++) acc[mi][ni][c] = 0.f;

  #pragma unroll
  for (int k0 = 0; k0 < 8; k0++) {
    const uint32_t ka = (uint32_t)k0 * 32;
    uint32_t A0[4], A1[4], B0[4], B1[4];
    LDSM_X4(A0, a0 + ka); LDSM_X4(A1, a1 + ka);
    LDSM_X4(B0, b0 + ka); LDSM_X4(B1, b1 + ka);
    MMA_F16(acc[0][0], A0, B0[0], B0[2]);
    MMA_F16(acc[0][1], A0, B0[1], B0[3]);
    MMA_F16(acc[0][2], A0, B1[0], B1[2]);
    MMA_F16(acc[0][3], A0, B1[1], B1[3]);
    MMA_F16(acc[1][0], A1, B0[0], B0[2]);
    MMA_F16(acc[1][1], A1, B0[1], B0[3]);
    MMA_F16(acc[1][2], A1, B1[0], B1[2]);
    MMA_F16(acc[1][3], A1, B1[1], B1[3]);
  }
}

// ---------------------------------------------------------------------------
// Fused layer-1: each CTA = up to 9 chunks x 128 edges of ONE relation.
// B staged once; single A buffer, stage(c+1) after mma-sync overlaps the
// epilogue. 4 CTAs/SM, single wave. Epilogue: shfl pair-merge -> red.v4.
// ---------------------------------------------------------------------------
__global__ void __launch_bounds__(256, 4) k_edge1_fused(
    const float* __restrict__ b1) {
  extern __shared__ char sm[];
  const uint32_t sb = smem_u32(sm);
  const int tid = threadIdx.x, wid = tid >> 5, lane = tid & 31;
  const int b = blockIdx.x;
  const int gridE = (int)gridDim.x - SLGRID;
  const bool is_edge = (b < gridE);

  int r, eoff = 0, eend = 0, cstart = 0, nch, n0 = 0;
  if (is_edge) {
    if (b >= __ldg(&g_cbase[N_RELS])) return;
    r = 0;
    while (b >= __ldg(&g_cbase[r + 1])) r++;
    eoff = __ldg(&g_off[r]);
    const int cnt = __ldg(&g_cnt[r]);
    eend = eoff + cnt;
    cstart = (b - __ldg(&g_cbase[r])) * NCH;
    nch = min(NCH, (cnt + ECH - 1) / ECH - cstart);
  } else {
    const int sl = b - gridE;
    r = N_RELS;
    n0 = sl * (NCH * ECH);
    nch = min(NCH, (N_NODES - n0 + ECH - 1) / ECH);
  }

  // Stage A chunk c: 128 rows x 16 x 16B cp.async (single buffer).
  auto stageA = [&](int c) {
    int ebase = 0, mm = 0;
    if (is_edge) {
      ebase = eoff + (cstart + c) * ECH;
      mm = min(ECH, eend - ebase);
    }
    #pragma unroll
    for (int t = 0; t < 8; t++) {
      int idx = tid + t * 256;
      int row = idx >> 4, cc = idx & 15;
      int s = is_edge ? __ldg(&g_esrc[ebase + min(row, mm - 1)])
                      : min(n0 + c * ECH + row, N_NODES - 1);
      CP16(sb + S_A0 + (uint32_t)row * (PITCH * 2) + (uint32_t)cc * 16,
           (const char*)g_featF + (size_t)s * 256 + cc * 16);
    }
  };

  // Prologue: B (1088 x 16B) + A0 in group 0.
  const char* wsrc = (const char*)(g_wimg + (size_t)r * WIMG);
  #pragma unroll
  for (int t = 0; t < 5; t++) {
    int idx = tid + t * 256;
    if (idx < WIMG * 2 / 16)
      CP16(sb + S_B + idx * 16, wsrc + idx * 16);
  }
  stageA(0);
  CP_COMMIT();

  const int g = lane >> 2, tq = lane & 3;
  const int mrow = (wid & 3) * 32, ncol = (wid >> 2) * 32;
  const int odd = tq & 1;                 // lane-pair role
  const int col4 = ncol + (tq >> 1) * 4;  // + ni*8 later

  for (int c = 0; c < nch; c++) {
    CP_WAIT0();
    __syncthreads();                 // A[c] (and B) visible
    float acc[2][4][4];
    mma_core(sb, wid, lane, acc);
    __syncthreads();                 // all warps done reading A[c]
    if (c + 1 < nch) { stageA(c + 1); CP_COMMIT(); }  // overlaps epilogue

    if (is_edge) {
      const int ebase = eoff + (cstart + c) * ECH;
      const int m = min(ECH, eend - ebase);
      #pragma unroll
      for (int mi = 0; mi < 2; mi++) {
        int row = mrow + mi * 16 + g + (odd ? 8 : 0);
        int d = (row < m) ? __ldg(&g_edst[ebase + row]) : -1;
        #pragma unroll
        for (int ni = 0; ni < 4; ni++) {
          float o0 = __shfl_xor_sync(0xffffffffu, acc[mi][ni][0], 1);
          float o1 = __shfl_xor_sync(0xffffffffu, acc[mi][ni][1], 1);
          float o2 = __shfl_xor_sync(0xffffffffu, acc[mi][ni][2], 1);
          float o3 = __shfl_xor_sync(0xffffffffu, acc[mi][ni][3], 1);
          if (d >= 0) {
            float4 v = odd
                ? make_float4(o2, o3, acc[mi][ni][2], acc[mi][ni][3])
                : make_float4(acc[mi][ni][0], acc[mi][ni][1], o0, o1);
            REDV4(g_h1 + (size_t)d * D_HID + col4 + ni * 8, v);
          }
        }
      }
    } else {
      const int nb = n0 + c * ECH;
      #pragma unroll
      for (int mi = 0; mi < 2; mi++) {
        int n = nb + mrow + mi * 16 + g + (odd ? 8 : 0);
        #pragma unroll
        for (int ni = 0; ni < 4; ni++) {
          float4 bias4 = __ldg((const float4*)(b1 + col4 + ni * 8));
          float o0 = __shfl_xor_sync(0xffffffffu, acc[mi][ni][0], 1);
          float o1 = __shfl_xor_sync(0xffffffffu, acc[mi][ni][1], 1);
          float o2 = __shfl_xor_sync(0xffffffffu, acc[mi][ni][2], 1);
          float o3 = __shfl_xor_sync(0xffffffffu, acc[mi][ni][3], 1);
          if (n < N_NODES) {
            float4 v = odd
                ? make_float4(o2 + bias4.x, o3 + bias4.y,
                              acc[mi][ni][2] + bias4.z,
                              acc[mi][ni][3] + bias4.w)
                : make_float4(acc[mi][ni][0] + bias4.x,
                              acc[mi][ni][1] + bias4.y,
                              o0 + bias4.z, o1 + bias4.w);
            REDV4(g_h1 + (size_t)n * D_HID + col4 + ni * 8, v);
          }
        }
      }
    }
  }
}

// ---------------------------------------------------------------------------
// Layer 2, single kernel (R15 version): edge blocks compute per-edge
// messages from L2-resident h1; tail node blocks add the self-loop term.
// All results red.v2 into pre-zeroed out.
// ---------------------------------------------------------------------------
__global__ void __launch_bounds__(256) k_layer2(
    const float* __restrict__ W2, const float* __restrict__ loop2,
    const float* __restrict__ b2, float* __restrict__ out) {
  __shared__ float2 sW[D_HID * 20];     // [k][r] pad 20
  __shared__ float2 sL[D_HID];
  __shared__ float2 sb2;
  __shared__ int so[N_RELS + 1];
  const int b = blockIdx.x;
  const bool is_edge = (b < EB);

  if (is_edge) {
    for (int i = threadIdx.x; i < D_HID * N_RELS; i += 256) {
      int k = i / N_RELS, r = i % N_RELS;
      sW[k * 20 + r] = *(const float2*)(W2 + ((size_t)r * D_HID + k) * D_OUT);
    }
    if (threadIdx.x < N_RELS + 1) so[threadIdx.x] = g_off[threadIdx.x];
  } else {
    if (threadIdx.x < D_HID)
      sL[threadIdx.x] = *(const float2*)(loop2 + threadIdx.x * 2);
    if (threadIdx.x == 64) sb2 = *(const float2*)b2;
  }
  __syncthreads();

  if (is_edge) {
    int e = b * 256 + threadIdx.x;
    if (e >= N_EDGES) return;
    int r = 0;
    #pragma unroll
    for (int rr = 1; rr < N_RELS; rr++)
      if (e >= so[rr]) r = rr;
    int s = __ldg(&g_esrc[e]), d = __ldg(&g_edst[e]);
    float a0 = 0.f, a1 = 0.f;
    const float4* hp = (const float4*)(g_h1 + (size_t)s * D_HID);
    #pragma unroll
    for (int kq = 0; kq < 16; kq++) {
      float4 v = __ldg(hp + kq);
      float x[4] = {v.x, v.y, v.z, v.w};
      #pragma unroll
      for (int j = 0; j < 4; j++) {
        float f = fmaxf(x[j], 0.f);
        float2 w = sW[(kq * 4 + j) * 20 + r];   // warp-uniform r -> broadcast
        a0 += f * w.x; a1 += f * w.y;
      }
    }
    REDV2(out + (size_t)d * D_OUT, a0, a1);
  } else {
    int n = (b - EB) * 256 + threadIdx.x;
    if (n >= N_NODES) return;
    float a0 = sb2.x, a1 = sb2.y;
    const float4* hp = (const float4*)(g_h1 + (size_t)n * D_HID);
    #pragma unroll
    for (int kq = 0; kq < 16; kq++) {
      float4 v = hp[kq];
      float x[4] = {v.x, v.y, v.z, v.w};
      #pragma unroll
      for (int j = 0; j < 4; j++) {
        float f = fmaxf(x[j], 0.f);
        float2 w = sL[kq * 4 + j];
        a0 += f * w.x; a1 += f * w.y;
      }
    }
    REDV2(out + (size_t)n * D_OUT, a0, a1);
  }
}

// ---------------------------------------------------------------------------
extern "C" void kernel_launch(void* const* d_in, const int* in_sizes, int n_in,
                              void* d_out, int out_size) {
  const float* feat  = (const float*)d_in[0];
  const float* W1    = (const float*)d_in[1];
  const float* loop1 = (const float*)d_in[2];
  const float* b1    = (const float*)d_in[3];
  const float* W2    = (const float*)d_in[4];
  const float* loop2 = (const float*)d_in[5];
  const float* b2    = (const float*)d_in[6];
  const int*   src   = (const int*)d_in[7];
  const int*   dst   = (const int*)d_in[8];
  const int*   et    = (const int*)d_in[9];
  float* out = (float*)d_out;

  cudaFuncSetAttribute(k_edge1_fused,
                       cudaFuncAttributeMaxDynamicSharedMemorySize, S_FTOT);

  // 1: prep (convert + zero h1/out/flags)   2: bucket (hist+prefix+scatter)
  k_prep<<<(PREP_TOT + 255) / 256, 256>>>(feat, W1, loop1, out);
  k_bucket<<<(N_EDGES + 2047) / 2048, 512>>>(src, dst, et);

  // 3: fused pipelined edge GEMM + self-loop
  k_edge1_fused<<<EGRID + SLGRID, 256, S_FTOT>>>(b1);

  // 4: layer 2 (edge messages + self term, single kernel)
  k_layer2<<<EB + NB, 256>>>(W2, loop2, b2, out);
}